// round 8
// baseline (speedup 1.0000x reference)
#include <cuda_runtime.h>
#include <stdint.h>

// PicMix: output = two index-function masks, no input read.
// Flattened: [mask_a (8,12,512,512) fp32][mask_b same]. 192 planes of 512x512.
// group g = (ch%12)/3; isB = second mask.
//   g0: a=1,b=0 | g1: a=(i%2==j%2) | g2: a=i%2 | g3: a=j%2 ; b = complement.
// Each 32B store covers j..j+7 (even start) -> lanes repeat (even,odd).
//
// R8: R7 sweep-optimum shape (12288 CTAs x 256 thr, 64B/thread) but with
// Blackwell 256-bit stores (st.global.v8.f32 -> STG.E.256): same bytes in
// half the store instructions / wavefront issues. Tests whether the ~65%
// plateau is wavefront-count limited vs byte limited.

static constexpr int PLANE_F4         = 65536;  // 512*512/4
static constexpr int BLOCKS_PER_PLANE = 64;
static constexpr int F4_PER_BLOCK     = PLANE_F4 / BLOCKS_PER_PLANE; // 1024
static constexpr int THREADS          = 256;
// Per thread: 2 x 32B stores. Thread t covers f4 indices {2t, 2t+1} and
// {2t+512, 2t+513} of its block -> 32B-aligned, stride 512 f4 = 8KB = 4 rows.

__device__ __forceinline__ void stg256(float4* p, float e, float o) {
    asm volatile(
        "st.global.v8.f32 [%0], {%1, %2, %3, %4, %5, %6, %7, %8};"
        :: "l"(p), "f"(e), "f"(o), "f"(e), "f"(o), "f"(e), "f"(o), "f"(e), "f"(o)
        : "memory");
}

__global__ void __launch_bounds__(THREADS) picmix_kernel(float4* __restrict__ out) {
    int plane = blockIdx.x >> 6;        // BLOCKS_PER_PLANE = 64
    int seg   = blockIdx.x & 63;

    // First store: f4 index base0 = blockBase + 2*t   (row = base0>>7)
    int blockBase = plane * PLANE_F4 + seg * F4_PER_BLOCK;
    int base0 = blockBase + 2 * threadIdx.x;
    int ip0   = (base0 >> 7) & 1;       // row parity of first store
    // Second store is +512 f4 = +4 rows -> same parity.

    int isB = plane >= 96;              // 96 planes per mask
    int pin = isB ? plane - 96 : plane;
    int ch  = pin % 12;
    int g   = ch * 0x5556 >> 16;        // ch/3 for ch in [0,12)

    float e, o;                         // even-j value, odd-j value
    if (g == 0) {
        e = o = isB ? 0.0f : 1.0f;
    } else if (g == 1) {
        float s = (ip0 == 0) ? 1.0f : 0.0f;  // mask_a even lane
        e = isB ? 1.0f - s : s;
        o = 1.0f - e;
    } else if (g == 2) {
        float v = (float)ip0;
        e = o = isB ? 1.0f - v : v;
    } else {
        e = isB ? 1.0f : 0.0f;
        o = 1.0f - e;
    }

    float4* p = out + base0;
    stg256(p, e, o);                    // f4 [base0, base0+1]
    stg256(p + 512, e, o);              // +8KB = 4 rows, same parity
}

extern "C" void kernel_launch(void* const* d_in, const int* in_sizes, int n_in,
                              void* d_out, int out_size) {
    (void)d_in; (void)in_sizes; (void)n_in; (void)out_size;
    // out_size = 50,331,648 fp32 = 192 planes * 65536 f4
    int blocks = 192 * BLOCKS_PER_PLANE;  // 12288
    picmix_kernel<<<blocks, THREADS>>>((float4*)d_out);
}